// round 1
// baseline (speedup 1.0000x reference)
#include <cuda_runtime.h>

#define NB 8
#define CI 256
#define TL 1024
#define EMB 512
#define OC 256
#define NH 8
#define DH 64
#define DVH 32

// Scratch (device globals — no allocation allowed)
__device__ float g_Q[NB*NH*TL*DH];   // (n,h,t,64)
__device__ float g_K[NB*NH*TL*DH];   // (n,h,t,64)
__device__ float g_V[NB*NH*TL*DVH];  // (n,h,t,32)
__device__ float g_A[NB*OC*TL];      // attention output, (n,c,t)

// ---------------------------------------------------------------------------
// Fused QKV projection:  Y[o][t] = sum_c W[o][c] * x[n][c][t] + b[o]
// o in [0,1280): [0,512)=Q, [512,1024)=K, [1024,1280)=V
// Scatter-store into multihead layouts.
// ---------------------------------------------------------------------------
__global__ __launch_bounds__(256) void qkv_gemm(
    const float* __restrict__ x,
    const float* __restrict__ Wq,  const float* __restrict__ bq,
    const float* __restrict__ Wkv, const float* __restrict__ bkv)
{
    __shared__ float As[16][65];   // [kk][m]
    __shared__ float Bs[16][65];   // [kk][t]
    const int n  = blockIdx.z;
    const int m0 = blockIdx.y * 64;
    const int t0 = blockIdx.x * 64;
    const int tid = threadIdx.x;
    const int tx = tid & 15, ty = tid >> 4;
    float acc[4][4] = {};
    const float* xb = x + (size_t)n * CI * TL;

    for (int k0 = 0; k0 < CI; k0 += 16) {
        #pragma unroll
        for (int l = 0; l < 4; l++) {
            int idx = tid + l * 256;
            int m = idx >> 4, kk = idx & 15;
            int o = m0 + m;
            As[kk][m] = (o < EMB) ? Wq[o*CI + k0 + kk]
                                  : Wkv[(o-EMB)*CI + k0 + kk];
        }
        #pragma unroll
        for (int l = 0; l < 4; l++) {
            int idx = tid + l * 256;
            int kk = idx >> 6, t = idx & 63;
            Bs[kk][t] = xb[(k0+kk)*TL + t0 + t];
        }
        __syncthreads();
        #pragma unroll
        for (int kk = 0; kk < 16; kk++) {
            float a[4], b[4];
            #pragma unroll
            for (int i = 0; i < 4; i++) a[i] = As[kk][ty*4+i];
            #pragma unroll
            for (int j = 0; j < 4; j++) b[j] = Bs[kk][tx*4+j];
            #pragma unroll
            for (int i = 0; i < 4; i++)
                #pragma unroll
                for (int j = 0; j < 4; j++)
                    acc[i][j] += a[i] * b[j];
        }
        __syncthreads();
    }

    #pragma unroll
    for (int i = 0; i < 4; i++) {
        int o = m0 + ty*4 + i;
        float bias = (o < EMB) ? bq[o] : bkv[o - EMB];
        #pragma unroll
        for (int j = 0; j < 4; j++) {
            int t = t0 + tx*4 + j;
            float v = acc[i][j] + bias;
            if (o < EMB) {
                int h = o >> 6, d = o & 63;
                g_Q[(((size_t)n*NH + h)*TL + t)*DH + d] = v;
            } else if (o < 2*EMB) {
                int oo = o - EMB;
                int h = oo >> 6, d = oo & 63;
                g_K[(((size_t)n*NH + h)*TL + t)*DH + d] = v;
            } else {
                int oo = o - 2*EMB;
                int h = oo >> 5, d = oo & 31;
                g_V[(((size_t)n*NH + h)*TL + t)*DVH + d] = v;
            }
        }
    }
}

// ---------------------------------------------------------------------------
// Causal flash attention. One block = one (n,h) pair x 64-row Q tile.
// Online softmax, fp32. dk=64 (scale 0.125), dv=32.
// ---------------------------------------------------------------------------
__global__ __launch_bounds__(256) void attn_kernel()
{
    extern __shared__ float sm[];
    float* Qs = sm;                 // 64 x 64  (broadcast reads -> no pad)
    float* Ks = Qs + 64*64;         // 64 x 65
    float* Ss = Ks + 64*65;         // 64 x 65
    float* Vs = Ss + 64*65;         // 64 x 33

    const int qtile = blockIdx.x;       // 0..15
    const int nh    = blockIdx.y;       // 0..63
    const int tid = threadIdx.x;
    const int tx = tid & 15, ty = tid >> 4;
    const float scale = 0.125f;         // 1/sqrt(64)

    const float* Qb = g_Q + ((size_t)nh*TL + qtile*64) * DH;
    const float* Kb = g_K + (size_t)nh*TL*DH;
    const float* Vb = g_V + (size_t)nh*TL*DVH;

    // Load Q tile (pre-scaled)
    #pragma unroll
    for (int l = 0; l < 16; l++) {
        int idx = tid + l*256;
        int r = idx >> 6, d = idx & 63;
        Qs[r*64 + d] = Qb[r*DH + d] * scale;
    }

    const int row  = tid >> 2;      // 0..63 (softmax/PV ownership)
    const int q4   = tid & 3;
    const int col0 = q4 * 8;
    float m_prev = -1e30f, l_sum = 0.0f;
    float oacc[8] = {0,0,0,0,0,0,0,0};

    __syncthreads();

    for (int j = 0; j <= qtile; j++) {
        const float* Kt = Kb + (size_t)j*64*DH;
        #pragma unroll
        for (int l = 0; l < 16; l++) {
            int idx = tid + l*256;
            int r = idx >> 6, d = idx & 63;
            Ks[r*65 + d] = Kt[r*DH + d];
        }
        const float* Vt = Vb + (size_t)j*64*DVH;
        #pragma unroll
        for (int l = 0; l < 8; l++) {
            int idx = tid + l*256;
            int r = idx >> 5, d = idx & 31;
            Vs[r*33 + d] = Vt[r*DVH + d];
        }
        __syncthreads();

        // S = Q K^T (already scaled via Q)
        float acc[4][4] = {};
        #pragma unroll 8
        for (int kk = 0; kk < 64; kk++) {
            float a[4], b[4];
            #pragma unroll
            for (int i = 0; i < 4; i++) a[i] = Qs[(ty*4+i)*64 + kk];
            #pragma unroll
            for (int jj = 0; jj < 4; jj++) b[jj] = Ks[(tx*4+jj)*65 + kk];
            #pragma unroll
            for (int i = 0; i < 4; i++)
                #pragma unroll
                for (int jj = 0; jj < 4; jj++)
                    acc[i][jj] += a[i] * b[jj];
        }
        const bool diag = (j == qtile);
        #pragma unroll
        for (int i = 0; i < 4; i++) {
            int r_ = ty*4 + i;
            #pragma unroll
            for (int jj = 0; jj < 4; jj++) {
                int c_ = tx*4 + jj;
                float s = acc[i][jj];
                if (diag && c_ > r_) s = -1e30f;
                Ss[r_*65 + c_] = s;
            }
        }
        // S writers/readers for a given row are the same 16-thread group -> warp sync
        __syncwarp();

        // online softmax: each thread scans its 16-col quarter of its row
        float mx = -1e30f;
        #pragma unroll
        for (int c = 0; c < 16; c++)
            mx = fmaxf(mx, Ss[row*65 + q4*16 + c]);
        mx = fmaxf(mx, __shfl_xor_sync(0xffffffffu, mx, 1));
        mx = fmaxf(mx, __shfl_xor_sync(0xffffffffu, mx, 2));
        float m_new = fmaxf(m_prev, mx);
        float alpha = __expf(m_prev - m_new);
        float psum = 0.0f;
        #pragma unroll
        for (int c = 0; c < 16; c++) {
            int off = row*65 + q4*16 + c;
            float p = __expf(Ss[off] - m_new);
            Ss[off] = p;
            psum += p;
        }
        psum += __shfl_xor_sync(0xffffffffu, psum, 1);
        psum += __shfl_xor_sync(0xffffffffu, psum, 2);
        l_sum = l_sum * alpha + psum;
        m_prev = m_new;
        #pragma unroll
        for (int jj = 0; jj < 8; jj++) oacc[jj] *= alpha;
        __syncwarp();

        // O += P @ V  (thread: row `row`, cols col0..col0+7)
        #pragma unroll 8
        for (int s = 0; s < 64; s++) {
            float p = Ss[row*65 + s];
            #pragma unroll
            for (int jj = 0; jj < 8; jj++)
                oacc[jj] += p * Vs[s*33 + col0 + jj];
        }
        __syncthreads();   // protect Ks/Vs/Ss before next tile's loads
    }

    // write normalized output into (n, c=h*32+d, t) layout
    float inv = 1.0f / l_sum;
    int n = nh >> 3, h = nh & 7;
    int tg = qtile*64 + row;
    #pragma unroll
    for (int jj = 0; jj < 8; jj++) {
        g_A[((size_t)n*OC + h*DVH + col0 + jj)*TL + tg] = oacc[jj] * inv;
    }
}

// ---------------------------------------------------------------------------
// Output projection: out[n][o][t] = sum_c Wo[o][c] * A[n][c][t] + bo[o]
// ---------------------------------------------------------------------------
__global__ __launch_bounds__(256) void oproj_gemm(
    const float* __restrict__ Wo, const float* __restrict__ bo,
    float* __restrict__ out)
{
    __shared__ float As[16][65];
    __shared__ float Bs[16][65];
    const int n  = blockIdx.z;
    const int m0 = blockIdx.y * 64;
    const int t0 = blockIdx.x * 64;
    const int tid = threadIdx.x;
    const int tx = tid & 15, ty = tid >> 4;
    float acc[4][4] = {};
    const float* Ab = g_A + (size_t)n * OC * TL;

    for (int k0 = 0; k0 < OC; k0 += 16) {
        #pragma unroll
        for (int l = 0; l < 4; l++) {
            int idx = tid + l * 256;
            int m = idx >> 4, kk = idx & 15;
            As[kk][m] = Wo[(m0+m)*OC + k0 + kk];
        }
        #pragma unroll
        for (int l = 0; l < 4; l++) {
            int idx = tid + l * 256;
            int kk = idx >> 6, t = idx & 63;
            Bs[kk][t] = Ab[(k0+kk)*TL + t0 + t];
        }
        __syncthreads();
        #pragma unroll
        for (int kk = 0; kk < 16; kk++) {
            float a[4], b[4];
            #pragma unroll
            for (int i = 0; i < 4; i++) a[i] = As[kk][ty*4+i];
            #pragma unroll
            for (int j = 0; j < 4; j++) b[j] = Bs[kk][tx*4+j];
            #pragma unroll
            for (int i = 0; i < 4; i++)
                #pragma unroll
                for (int j = 0; j < 4; j++)
                    acc[i][j] += a[i] * b[j];
        }
        __syncthreads();
    }

    #pragma unroll
    for (int i = 0; i < 4; i++) {
        int o = m0 + ty*4 + i;
        float bias = bo[o];
        #pragma unroll
        for (int j = 0; j < 4; j++) {
            int t = t0 + tx*4 + j;
            out[((size_t)n*OC + o)*TL + t] = acc[i][j] + bias;
        }
    }
}

// ---------------------------------------------------------------------------
extern "C" void kernel_launch(void* const* d_in, const int* in_sizes, int n_in,
                              void* d_out, int out_size)
{
    const float* x   = (const float*)d_in[0];
    const float* Wq  = (const float*)d_in[1];
    const float* bq  = (const float*)d_in[2];
    const float* Wkv = (const float*)d_in[3];
    const float* bkv = (const float*)d_in[4];
    const float* Wo  = (const float*)d_in[5];
    const float* bo  = (const float*)d_in[6];
    float* out = (float*)d_out;

    // 1) QKV projection: M=1280 (20 tiles), N=1024 (16 tiles), per-batch
    dim3 g1(16, 20, NB);
    qkv_gemm<<<g1, 256>>>(x, Wq, bq, Wkv, bkv);

    // 2) flash attention (dynamic smem > 48KB -> opt in)
    size_t smem = (size_t)(64*64 + 64*65 + 64*65 + 64*33) * sizeof(float);
    cudaFuncSetAttribute(attn_kernel,
                         cudaFuncAttributeMaxDynamicSharedMemorySize, (int)smem);
    attn_kernel<<<dim3(16, 64), 256, smem>>>();

    // 3) output projection: M=256 (4 tiles), N=1024 (16 tiles)
    dim3 g3(16, 4, NB);
    oproj_gemm<<<g3, 256>>>(Wo, bo, out);
}

// round 2
// speedup vs baseline: 3.0940x; 3.0940x over previous
#include <cuda_runtime.h>

#define NB 8
#define CI 256
#define TL 1024
#define EMB 512
#define OC 256
#define NH 8
#define DH 64
#define DVH 32

// Scratch (device globals — no allocation allowed)
__device__ float g_Q[NB*NH*TL*DH];   // (n,h,t,64)
__device__ float g_K[NB*NH*TL*DH];   // (n,h,t,64)
__device__ float g_V[NB*NH*TL*DVH];  // (n,h,t,32)
__device__ float g_A[NB*OC*TL];      // attention output, (n,c,t)

// ---------------------------------------------------------------------------
// tf32 helpers
// ---------------------------------------------------------------------------
__device__ __forceinline__ float f2tf(float f) {
    unsigned u;
    asm("cvt.rna.tf32.f32 %0, %1;" : "=r"(u) : "f"(f));
    return __uint_as_float(u);
}

__device__ __forceinline__ void mma_tf32(float c[4], const unsigned a[4], const unsigned b[2]) {
    asm volatile(
        "mma.sync.aligned.m16n8k8.row.col.f32.tf32.tf32.f32 "
        "{%0,%1,%2,%3}, {%4,%5,%6,%7}, {%8,%9}, {%0,%1,%2,%3};"
        : "+f"(c[0]), "+f"(c[1]), "+f"(c[2]), "+f"(c[3])
        : "r"(a[0]), "r"(a[1]), "r"(a[2]), "r"(a[3]),
          "r"(b[0]), "r"(b[1]));
}

// ---------------------------------------------------------------------------
// QKV projection (tensor cores): Y[o][t] = sum_c W[o][c]*x[n][c][t] + b[o]
// CTA tile 64(M) x 128(N), 8 warps of 32x32. K chunks of 32.
// ---------------------------------------------------------------------------
__global__ __launch_bounds__(256) void qkv_mma(
    const float* __restrict__ x,
    const float* __restrict__ Wq,  const float* __restrict__ bq,
    const float* __restrict__ Wkv, const float* __restrict__ bkv)
{
    __shared__ float As[64][36];    // [m][k], stride 36 -> frag loads conflict-free
    __shared__ float Bs[32][136];   // [k][n], stride 136 -> conflict-free

    const int n  = blockIdx.z;
    const int m0 = blockIdx.y * 64;
    const int t0 = blockIdx.x * 128;
    const int tid = threadIdx.x;
    const int wid = tid >> 5, lane = tid & 31;
    const int g = lane >> 2, tg = lane & 3;
    const int wm = wid & 1, wn = wid >> 1;   // warp tile: rows wm*32, cols wn*32
    const float* xb = x + (size_t)n * CI * TL;

    float C[2][4][4] = {};

    for (int k0 = 0; k0 < CI; k0 += 32) {
        // A: 64 rows x 32 k
        #pragma unroll
        for (int l = 0; l < 2; l++) {
            int slot = tid + l*256;          // 512 float4 slots
            int m = slot >> 3, kg = slot & 7;
            int o = m0 + m;
            const float* Wr = (o < EMB) ? (Wq + (size_t)o*CI) : (Wkv + (size_t)(o-EMB)*CI);
            float4 v = *(const float4*)(Wr + k0 + kg*4);
            As[m][kg*4+0] = f2tf(v.x);
            As[m][kg*4+1] = f2tf(v.y);
            As[m][kg*4+2] = f2tf(v.z);
            As[m][kg*4+3] = f2tf(v.w);
        }
        // B: 32 k x 128 t
        #pragma unroll
        for (int l = 0; l < 4; l++) {
            int slot = tid + l*256;          // 1024 float4 slots
            int k = slot >> 5, ng = slot & 31;
            float4 v = *(const float4*)(xb + (size_t)(k0+k)*TL + t0 + ng*4);
            Bs[k][ng*4+0] = f2tf(v.x);
            Bs[k][ng*4+1] = f2tf(v.y);
            Bs[k][ng*4+2] = f2tf(v.z);
            Bs[k][ng*4+3] = f2tf(v.w);
        }
        __syncthreads();

        #pragma unroll
        for (int ks = 0; ks < 4; ks++) {
            const int kk = ks * 8;
            unsigned a[2][4];
            #pragma unroll
            for (int i = 0; i < 2; i++) {
                int r = wm*32 + i*16 + g;
                a[i][0] = __float_as_uint(As[r  ][kk+tg  ]);
                a[i][1] = __float_as_uint(As[r+8][kk+tg  ]);
                a[i][2] = __float_as_uint(As[r  ][kk+tg+4]);
                a[i][3] = __float_as_uint(As[r+8][kk+tg+4]);
            }
            unsigned b[4][2];
            #pragma unroll
            for (int j = 0; j < 4; j++) {
                int c = wn*32 + j*8 + g;
                b[j][0] = __float_as_uint(Bs[kk+tg  ][c]);
                b[j][1] = __float_as_uint(Bs[kk+tg+4][c]);
            }
            #pragma unroll
            for (int i = 0; i < 2; i++)
                #pragma unroll
                for (int j = 0; j < 4; j++)
                    mma_tf32(C[i][j], a[i], b[j]);
        }
        __syncthreads();
    }

    // epilogue: bias + scatter into multihead layouts
    #pragma unroll
    for (int i = 0; i < 2; i++) {
        #pragma unroll
        for (int j = 0; j < 4; j++) {
            #pragma unroll
            for (int v = 0; v < 4; v++) {
                int o = m0 + wm*32 + i*16 + g + ((v >= 2) ? 8 : 0);
                int t = t0 + wn*32 + j*8 + tg*2 + (v & 1);
                float bias = (o < EMB) ? bq[o] : bkv[o - EMB];
                float val = C[i][j][v] + bias;
                if (o < EMB) {
                    int h = o >> 6, d = o & 63;
                    g_Q[(((size_t)n*NH + h)*TL + t)*DH + d] = val;
                } else if (o < 2*EMB) {
                    int oo = o - EMB;
                    int h = oo >> 6, d = oo & 63;
                    g_K[(((size_t)n*NH + h)*TL + t)*DH + d] = val;
                } else {
                    int oo = o - 2*EMB;
                    int h = oo >> 5, d = oo & 31;
                    g_V[(((size_t)n*NH + h)*TL + t)*DVH + d] = val;
                }
            }
        }
    }
}

// ---------------------------------------------------------------------------
// Causal flash attention with tensor cores.
// One block = one (n,h) x 64-row Q tile; 256 threads (8 warps).
// QK^T: warp = 16(m) x 32(n);  PV: warp = 16(m) x 16(n).
// ---------------------------------------------------------------------------
__global__ __launch_bounds__(256) void attn_mma()
{
    extern __shared__ float sm[];
    float* Qs = sm;               // 64 x 68 (tf32-rounded, pre-scaled)
    float* Ks = Qs + 64*68;       // 64 x 68
    float* Ss = Ks + 64*68;       // 64 x 68  (S, then P)
    float* Vs = Ss + 64*68;       // 64 x 36
    float* Al = Vs + 64*36;       // 64 alphas (reused for 1/l at the end)

    const int qtile = blockIdx.x;   // 0..15
    const int nh    = blockIdx.y;   // 0..63
    const int tid = threadIdx.x;
    const int wid = tid >> 5, lane = tid & 31;
    const int g = lane >> 2, tg = lane & 3;
    const int wr = wid >> 1;        // 0..3: 16-row group (both phases)
    const int wc = wid & 1;         // QK: 32-col group; PV: 16-col group

    const float* Qb = g_Q + ((size_t)nh*TL + qtile*64) * DH;
    const float* Kb = g_K + (size_t)nh*TL*DH;
    const float* Vb = g_V + (size_t)nh*TL*DVH;

    // Load Q tile (scale 1/sqrt(64)=0.125 folded in, exact)
    #pragma unroll
    for (int l = 0; l < 4; l++) {
        int slot = tid + l*256;          // 1024 float4 slots
        int s = slot >> 4, dg = slot & 15;
        float4 v = *(const float4*)(Qb + (size_t)s*DH + dg*4);
        Qs[s*68 + dg*4+0] = f2tf(v.x * 0.125f);
        Qs[s*68 + dg*4+1] = f2tf(v.y * 0.125f);
        Qs[s*68 + dg*4+2] = f2tf(v.z * 0.125f);
        Qs[s*68 + dg*4+3] = f2tf(v.w * 0.125f);
    }

    // softmax ownership: 4 threads per row
    const int row = tid >> 2;
    const int q4  = tid & 3;
    float m_prev = -1e30f, l_sum = 0.0f;

    float O[2][4] = {};   // PV accumulators: [n-tile][frag], persist across j

    __syncthreads();

    for (int j = 0; j <= qtile; j++) {
        // ---- load K (64x64) and V (64x32) tiles ----
        const float* Kt = Kb + (size_t)j*64*DH;
        #pragma unroll
        for (int l = 0; l < 4; l++) {
            int slot = tid + l*256;
            int s = slot >> 4, dg = slot & 15;
            float4 v = *(const float4*)(Kt + (size_t)s*DH + dg*4);
            Ks[s*68 + dg*4+0] = f2tf(v.x);
            Ks[s*68 + dg*4+1] = f2tf(v.y);
            Ks[s*68 + dg*4+2] = f2tf(v.z);
            Ks[s*68 + dg*4+3] = f2tf(v.w);
        }
        const float* Vt = Vb + (size_t)j*64*DVH;
        #pragma unroll
        for (int l = 0; l < 2; l++) {
            int slot = tid + l*256;          // 512 float4 slots
            int s = slot >> 3, dg = slot & 7;
            float4 v = *(const float4*)(Vt + (size_t)s*DVH + dg*4);
            Vs[s*36 + dg*4+0] = f2tf(v.x);
            Vs[s*36 + dg*4+1] = f2tf(v.y);
            Vs[s*36 + dg*4+2] = f2tf(v.z);
            Vs[s*36 + dg*4+3] = f2tf(v.w);
        }
        __syncthreads();

        // ---- S = Q K^T (warp: rows wr*16, cols wc*32, 4 n-tiles) ----
        float S[4][4] = {};
        #pragma unroll
        for (int ks = 0; ks < 8; ks++) {
            const int kk = ks * 8;
            unsigned a[4];
            {
                int r = wr*16 + g;
                a[0] = __float_as_uint(Qs[(r  )*68 + kk+tg  ]);
                a[1] = __float_as_uint(Qs[(r+8)*68 + kk+tg  ]);
                a[2] = __float_as_uint(Qs[(r  )*68 + kk+tg+4]);
                a[3] = __float_as_uint(Qs[(r+8)*68 + kk+tg+4]);
            }
            unsigned b[4][2];
            #pragma unroll
            for (int jn = 0; jn < 4; jn++) {
                int c = wc*32 + jn*8 + g;
                b[jn][0] = __float_as_uint(Ks[c*68 + kk+tg  ]);
                b[jn][1] = __float_as_uint(Ks[c*68 + kk+tg+4]);
            }
            #pragma unroll
            for (int jn = 0; jn < 4; jn++)
                mma_tf32(S[jn], a, b[jn]);
        }
        // write S to smem with causal mask
        const bool diag = (j == qtile);
        #pragma unroll
        for (int jn = 0; jn < 4; jn++) {
            int r  = wr*16 + g;
            int c  = wc*32 + jn*8 + tg*2;
            float s0 = S[jn][0], s1 = S[jn][1], s2 = S[jn][2], s3 = S[jn][3];
            if (diag) {
                if (c   > r  ) s0 = -1e30f;
                if (c+1 > r  ) s1 = -1e30f;
                if (c   > r+8) s2 = -1e30f;
                if (c+1 > r+8) s3 = -1e30f;
            }
            Ss[(r  )*68 + c  ] = s0;
            Ss[(r  )*68 + c+1] = s1;
            Ss[(r+8)*68 + c  ] = s2;
            Ss[(r+8)*68 + c+1] = s3;
        }
        __syncthreads();

        // ---- online softmax (4 threads per row) ----
        float mx = -1e30f;
        #pragma unroll
        for (int c = 0; c < 16; c++)
            mx = fmaxf(mx, Ss[row*68 + q4*16 + c]);
        mx = fmaxf(mx, __shfl_xor_sync(0xffffffffu, mx, 1));
        mx = fmaxf(mx, __shfl_xor_sync(0xffffffffu, mx, 2));
        float m_new = fmaxf(m_prev, mx);
        float alpha = __expf(m_prev - m_new);
        float psum = 0.0f;
        #pragma unroll
        for (int c = 0; c < 16; c++) {
            int off = row*68 + q4*16 + c;
            float p = f2tf(__expf(Ss[off] - m_new));   // round to tf32 for PV
            Ss[off] = p;
            psum += p;
        }
        psum += __shfl_xor_sync(0xffffffffu, psum, 1);
        psum += __shfl_xor_sync(0xffffffffu, psum, 2);
        l_sum = l_sum * alpha + psum;
        m_prev = m_new;
        if (q4 == 0) Al[row] = alpha;
        __syncthreads();

        // ---- O = alpha*O + P V (warp: rows wr*16, cols wc*16, 2 n-tiles) ----
        {
            float a_lo = Al[wr*16 + g];
            float a_hi = Al[wr*16 + g + 8];
            #pragma unroll
            for (int jn = 0; jn < 2; jn++) {
                O[jn][0] *= a_lo; O[jn][1] *= a_lo;
                O[jn][2] *= a_hi; O[jn][3] *= a_hi;
            }
        }
        #pragma unroll
        for (int ks = 0; ks < 8; ks++) {
            const int kk = ks * 8;
            unsigned a[4];
            {
                int r = wr*16 + g;
                a[0] = __float_as_uint(Ss[(r  )*68 + kk+tg  ]);
                a[1] = __float_as_uint(Ss[(r+8)*68 + kk+tg  ]);
                a[2] = __float_as_uint(Ss[(r  )*68 + kk+tg+4]);
                a[3] = __float_as_uint(Ss[(r+8)*68 + kk+tg+4]);
            }
            unsigned b[2][2];
            #pragma unroll
            for (int jn = 0; jn < 2; jn++) {
                int c = wc*16 + jn*8 + g;
                b[jn][0] = __float_as_uint(Vs[(kk+tg  )*36 + c]);
                b[jn][1] = __float_as_uint(Vs[(kk+tg+4)*36 + c]);
            }
            #pragma unroll
            for (int jn = 0; jn < 2; jn++)
                mma_tf32(O[jn], a, b[jn]);
        }
        __syncthreads();   // protect Ks/Vs/Ss before next tile
    }

    // publish 1/l per row
    if (q4 == 0) Al[row] = 1.0f / l_sum;
    __syncthreads();

    // normalize + store to g_A (n, c=h*32+d, t)
    const int n = nh >> 3, h = nh & 7;
    const float inv_lo = Al[wr*16 + g];
    const float inv_hi = Al[wr*16 + g + 8];
    const int t_lo = qtile*64 + wr*16 + g;
    const int t_hi = t_lo + 8;
    #pragma unroll
    for (int jn = 0; jn < 2; jn++) {
        int ch = h*DVH + wc*16 + jn*8 + tg*2;
        g_A[((size_t)n*OC + ch  )*TL + t_lo] = O[jn][0] * inv_lo;
        g_A[((size_t)n*OC + ch+1)*TL + t_lo] = O[jn][1] * inv_lo;
        g_A[((size_t)n*OC + ch  )*TL + t_hi] = O[jn][2] * inv_hi;
        g_A[((size_t)n*OC + ch+1)*TL + t_hi] = O[jn][3] * inv_hi;
    }
}

// ---------------------------------------------------------------------------
// Output projection (tensor cores): out[n][o][t] = sum_c Wo[o][c]*A[n][c][t]+bo
// ---------------------------------------------------------------------------
__global__ __launch_bounds__(256) void oproj_mma(
    const float* __restrict__ Wo, const float* __restrict__ bo,
    float* __restrict__ out)
{
    __shared__ float As[64][36];
    __shared__ float Bs[32][136];

    const int n  = blockIdx.z;
    const int m0 = blockIdx.y * 64;
    const int t0 = blockIdx.x * 128;
    const int tid = threadIdx.x;
    const int wid = tid >> 5, lane = tid & 31;
    const int g = lane >> 2, tg = lane & 3;
    const int wm = wid & 1, wn = wid >> 1;
    const float* Ab = g_A + (size_t)n * OC * TL;

    float C[2][4][4] = {};

    for (int k0 = 0; k0 < OC; k0 += 32) {
        #pragma unroll
        for (int l = 0; l < 2; l++) {
            int slot = tid + l*256;
            int m = slot >> 3, kg = slot & 7;
            float4 v = *(const float4*)(Wo + (size_t)(m0+m)*OC + k0 + kg*4);
            As[m][kg*4+0] = f2tf(v.x);
            As[m][kg*4+1] = f2tf(v.y);
            As[m][kg*4+2] = f2tf(v.z);
            As[m][kg*4+3] = f2tf(v.w);
        }
        #pragma unroll
        for (int l = 0; l < 4; l++) {
            int slot = tid + l*256;
            int k = slot >> 5, ng = slot & 31;
            float4 v = *(const float4*)(Ab + (size_t)(k0+k)*TL + t0 + ng*4);
            Bs[k][ng*4+0] = f2tf(v.x);
            Bs[k][ng*4+1] = f2tf(v.y);
            Bs[k][ng*4+2] = f2tf(v.z);
            Bs[k][ng*4+3] = f2tf(v.w);
        }
        __syncthreads();

        #pragma unroll
        for (int ks = 0; ks < 4; ks++) {
            const int kk = ks * 8;
            unsigned a[2][4];
            #pragma unroll
            for (int i = 0; i < 2; i++) {
                int r = wm*32 + i*16 + g;
                a[i][0] = __float_as_uint(As[r  ][kk+tg  ]);
                a[i][1] = __float_as_uint(As[r+8][kk+tg  ]);
                a[i][2] = __float_as_uint(As[r  ][kk+tg+4]);
                a[i][3] = __float_as_uint(As[r+8][kk+tg+4]);
            }
            unsigned b[4][2];
            #pragma unroll
            for (int j = 0; j < 4; j++) {
                int c = wn*32 + j*8 + g;
                b[j][0] = __float_as_uint(Bs[kk+tg  ][c]);
                b[j][1] = __float_as_uint(Bs[kk+tg+4][c]);
            }
            #pragma unroll
            for (int i = 0; i < 2; i++)
                #pragma unroll
                for (int j = 0; j < 4; j++)
                    mma_tf32(C[i][j], a[i], b[j]);
        }
        __syncthreads();
    }

    #pragma unroll
    for (int i = 0; i < 2; i++) {
        int r0 = m0 + wm*32 + i*16 + g;
        float b_lo = bo[r0], b_hi = bo[r0+8];
        #pragma unroll
        for (int j = 0; j < 4; j++) {
            int c = t0 + wn*32 + j*8 + tg*2;
            out[((size_t)n*OC + r0  )*TL + c  ] = C[i][j][0] + b_lo;
            out[((size_t)n*OC + r0  )*TL + c+1] = C[i][j][1] + b_lo;
            out[((size_t)n*OC + r0+8)*TL + c  ] = C[i][j][2] + b_hi;
            out[((size_t)n*OC + r0+8)*TL + c+1] = C[i][j][3] + b_hi;
        }
    }
}

// ---------------------------------------------------------------------------
extern "C" void kernel_launch(void* const* d_in, const int* in_sizes, int n_in,
                              void* d_out, int out_size)
{
    const float* x   = (const float*)d_in[0];
    const float* Wq  = (const float*)d_in[1];
    const float* bq  = (const float*)d_in[2];
    const float* Wkv = (const float*)d_in[3];
    const float* bkv = (const float*)d_in[4];
    const float* Wo  = (const float*)d_in[5];
    const float* bo  = (const float*)d_in[6];
    float* out = (float*)d_out;

    // 1) QKV: M=1280 (20 tiles of 64), N=1024 (8 tiles of 128), per batch
    qkv_mma<<<dim3(8, 20, NB), 256>>>(x, Wq, bq, Wkv, bkv);

    // 2) flash attention (dynamic smem)
    size_t smem = (size_t)(3*64*68 + 64*36 + 64) * sizeof(float);
    cudaFuncSetAttribute(attn_mma,
                         cudaFuncAttributeMaxDynamicSharedMemorySize, (int)smem);
    attn_mma<<<dim3(16, 64), 256, smem>>>();

    // 3) O proj: M=256 (4 tiles), N=1024 (8 tiles)
    oproj_mma<<<dim3(8, 4, NB), 256>>>(Wo, bo, out);
}

// round 3
// speedup vs baseline: 3.7883x; 1.2244x over previous
#include <cuda_runtime.h>

#define NB 8
#define CI 256
#define TL 1024
#define EMB 512
#define OC 256
#define NH 8
#define DH 64
#define DVH 32

// Scratch (device globals — no allocation allowed)
__device__ float g_Q[NB*NH*TL*DH];   // (n,h,t,64)
__device__ float g_K[NB*NH*TL*DH];   // (n,h,t,64)
__device__ float g_V[NB*NH*TL*DVH];  // (n,h,t,32)
__device__ float g_A[NB*OC*TL];      // attention output, (n,c,t)

// ---------------------------------------------------------------------------
// tf32 helpers
// ---------------------------------------------------------------------------
__device__ __forceinline__ float f2tf(float f) {
    unsigned u;
    asm("cvt.rna.tf32.f32 %0, %1;" : "=r"(u) : "f"(f));
    return __uint_as_float(u);
}

__device__ __forceinline__ void mma_tf32(float c[4], const unsigned a[4], const unsigned b[2]) {
    asm volatile(
        "mma.sync.aligned.m16n8k8.row.col.f32.tf32.tf32.f32 "
        "{%0,%1,%2,%3}, {%4,%5,%6,%7}, {%8,%9}, {%0,%1,%2,%3};"
        : "+f"(c[0]), "+f"(c[1]), "+f"(c[2]), "+f"(c[3])
        : "r"(a[0]), "r"(a[1]), "r"(a[2]), "r"(a[3]),
          "r"(b[0]), "r"(b[1]));
}

// ---------------------------------------------------------------------------
// QKV projection (tensor cores): Y[o][t] = sum_c W[o][c]*x[n][c][t] + b[o]
// CTA tile 64(M) x 128(N), 8 warps of 32x32. K chunks of 32.
// ---------------------------------------------------------------------------
__global__ __launch_bounds__(256) void qkv_mma(
    const float* __restrict__ x,
    const float* __restrict__ Wq,  const float* __restrict__ bq,
    const float* __restrict__ Wkv, const float* __restrict__ bkv)
{
    __shared__ float As[64][36];    // [m][k]
    __shared__ float Bs[32][136];   // [k][n]

    const int n  = blockIdx.z;
    const int m0 = blockIdx.y * 64;
    const int t0 = blockIdx.x * 128;
    const int tid = threadIdx.x;
    const int wid = tid >> 5, lane = tid & 31;
    const int g = lane >> 2, tg = lane & 3;
    const int wm = wid & 1, wn = wid >> 1;
    const float* xb = x + (size_t)n * CI * TL;

    float C[2][4][4] = {};

    for (int k0 = 0; k0 < CI; k0 += 32) {
        #pragma unroll
        for (int l = 0; l < 2; l++) {
            int slot = tid + l*256;
            int m = slot >> 3, kg = slot & 7;
            int o = m0 + m;
            const float* Wr = (o < EMB) ? (Wq + (size_t)o*CI) : (Wkv + (size_t)(o-EMB)*CI);
            float4 v = *(const float4*)(Wr + k0 + kg*4);
            As[m][kg*4+0] = f2tf(v.x);
            As[m][kg*4+1] = f2tf(v.y);
            As[m][kg*4+2] = f2tf(v.z);
            As[m][kg*4+3] = f2tf(v.w);
        }
        #pragma unroll
        for (int l = 0; l < 4; l++) {
            int slot = tid + l*256;
            int k = slot >> 5, ng = slot & 31;
            float4 v = *(const float4*)(xb + (size_t)(k0+k)*TL + t0 + ng*4);
            Bs[k][ng*4+0] = f2tf(v.x);
            Bs[k][ng*4+1] = f2tf(v.y);
            Bs[k][ng*4+2] = f2tf(v.z);
            Bs[k][ng*4+3] = f2tf(v.w);
        }
        __syncthreads();

        #pragma unroll
        for (int ks = 0; ks < 4; ks++) {
            const int kk = ks * 8;
            unsigned a[2][4];
            #pragma unroll
            for (int i = 0; i < 2; i++) {
                int r = wm*32 + i*16 + g;
                a[i][0] = __float_as_uint(As[r  ][kk+tg  ]);
                a[i][1] = __float_as_uint(As[r+8][kk+tg  ]);
                a[i][2] = __float_as_uint(As[r  ][kk+tg+4]);
                a[i][3] = __float_as_uint(As[r+8][kk+tg+4]);
            }
            unsigned b[4][2];
            #pragma unroll
            for (int j = 0; j < 4; j++) {
                int c = wn*32 + j*8 + g;
                b[j][0] = __float_as_uint(Bs[kk+tg  ][c]);
                b[j][1] = __float_as_uint(Bs[kk+tg+4][c]);
            }
            #pragma unroll
            for (int i = 0; i < 2; i++)
                #pragma unroll
                for (int j = 0; j < 4; j++)
                    mma_tf32(C[i][j], a[i], b[j]);
        }
        __syncthreads();
    }

    #pragma unroll
    for (int i = 0; i < 2; i++) {
        #pragma unroll
        for (int j = 0; j < 4; j++) {
            #pragma unroll
            for (int v = 0; v < 4; v++) {
                int o = m0 + wm*32 + i*16 + g + ((v >= 2) ? 8 : 0);
                int t = t0 + wn*32 + j*8 + tg*2 + (v & 1);
                float bias = (o < EMB) ? bq[o] : bkv[o - EMB];
                float val = C[i][j][v] + bias;
                if (o < EMB) {
                    int h = o >> 6, d = o & 63;
                    g_Q[(((size_t)n*NH + h)*TL + t)*DH + d] = val;
                } else if (o < 2*EMB) {
                    int oo = o - EMB;
                    int h = oo >> 6, d = oo & 63;
                    g_K[(((size_t)n*NH + h)*TL + t)*DH + d] = val;
                } else {
                    int oo = o - 2*EMB;
                    int h = oo >> 5, d = oo & 31;
                    g_V[(((size_t)n*NH + h)*TL + t)*DVH + d] = val;
                }
            }
        }
    }
}

// ---------------------------------------------------------------------------
// Causal flash attention, FA2-style: S/P live entirely in registers.
// Q tile = 128 rows; 8 warps, each owns 16 rows x full 64-col KV tile.
// Only K/V pass through smem (2 barriers per KV tile).
// ---------------------------------------------------------------------------
__global__ __launch_bounds__(256) void attn_mma2()
{
    extern __shared__ float sm[];
    float* Qs = sm;               // 128 x 68 (only before main loop)
    float* Ks = sm;               // 64 x 68 (overlays Qs after extraction)
    float* Vs = sm + 64*68;       // 64 x 40 (stride 40 -> conflict-free B frags)

    const int qtile = 7 - blockIdx.x;   // heavy tiles first
    const int nh    = blockIdx.y;
    const int tid = threadIdx.x;
    const int wid = tid >> 5, lane = tid & 31;
    const int g = lane >> 2, tg = lane & 3;
    const bool odd = (tg & 1);
    const int sbase = lane & ~3;
    const int s0l = sbase + (tg >> 1);      // shfl src for col tg
    const int s1l = s0l + 2;                // shfl src for col tg+4

    const float* Qb = g_Q + ((size_t)nh*TL + qtile*128) * DH;
    const float* Kb = g_K + (size_t)nh*TL*DH;
    const float* Vb = g_V + (size_t)nh*TL*DVH;

    // ---- load Q tile 128x64 into smem (tf32, pre-scaled by 1/8) ----
    #pragma unroll
    for (int l = 0; l < 8; l++) {
        int slot = tid + l*256;              // 2048 float4 slots
        int s = slot >> 4, dg = slot & 15;
        float4 v = *(const float4*)(Qb + (size_t)s*DH + dg*4);
        float4 w;
        w.x = f2tf(v.x * 0.125f); w.y = f2tf(v.y * 0.125f);
        w.z = f2tf(v.z * 0.125f); w.w = f2tf(v.w * 0.125f);
        *(float4*)&Qs[s*68 + dg*4] = w;
    }
    __syncthreads();

    // ---- extract Q fragments (persist in registers) ----
    unsigned Aq[8][4];
    {
        const int r = wid*16 + g;
        #pragma unroll
        for (int kt = 0; kt < 8; kt++) {
            const int kk = kt*8;
            Aq[kt][0] = __float_as_uint(Qs[(r  )*68 + kk+tg  ]);
            Aq[kt][1] = __float_as_uint(Qs[(r+8)*68 + kk+tg  ]);
            Aq[kt][2] = __float_as_uint(Qs[(r  )*68 + kk+tg+4]);
            Aq[kt][3] = __float_as_uint(Qs[(r+8)*68 + kk+tg+4]);
        }
    }
    __syncthreads();   // Qs region can now be reused for K

    float m0 = -1e30f, m1 = -1e30f, l0 = 0.0f, l1 = 0.0f;
    float O[4][4] = {};

    const int jmax = 2*qtile + 1;
    for (int j = 0; j <= jmax; j++) {
        // ---- load K (64x64) and V (64x32) tiles ----
        const float* Kt = Kb + (size_t)j*64*DH;
        #pragma unroll
        for (int l = 0; l < 4; l++) {
            int slot = tid + l*256;
            int s = slot >> 4, dg = slot & 15;
            float4 v = *(const float4*)(Kt + (size_t)s*DH + dg*4);
            float4 w;
            w.x = f2tf(v.x); w.y = f2tf(v.y); w.z = f2tf(v.z); w.w = f2tf(v.w);
            *(float4*)&Ks[s*68 + dg*4] = w;
        }
        const float* Vt = Vb + (size_t)j*64*DVH;
        #pragma unroll
        for (int l = 0; l < 2; l++) {
            int slot = tid + l*256;
            int s = slot >> 3, dg = slot & 7;
            float4 v = *(const float4*)(Vt + (size_t)s*DVH + dg*4);
            float4 w;
            w.x = f2tf(v.x); w.y = f2tf(v.y); w.z = f2tf(v.z); w.w = f2tf(v.w);
            *(float4*)&Vs[s*40 + dg*4] = w;
        }
        __syncthreads();

        // ---- S = Q K^T: warp strip 16 x 64 ----
        float S[8][4] = {};
        #pragma unroll
        for (int kt = 0; kt < 8; kt++) {
            const int kk = kt*8;
            #pragma unroll
            for (int nt = 0; nt < 8; nt++) {
                const int c = nt*8 + g;
                unsigned b[2];
                b[0] = __float_as_uint(Ks[c*68 + kk+tg  ]);
                b[1] = __float_as_uint(Ks[c*68 + kk+tg+4]);
                mma_tf32(S[nt], Aq[kt], b);
            }
        }

        // ---- causal mask (only near the diagonal) ----
        if (j >= 2*qtile) {
            const int gr0 = qtile*128 + wid*16 + g;
            const int gr1 = gr0 + 8;
            #pragma unroll
            for (int nt = 0; nt < 8; nt++) {
                const int gc = j*64 + nt*8 + tg*2;
                if (gc   > gr0) S[nt][0] = -1e30f;
                if (gc+1 > gr0) S[nt][1] = -1e30f;
                if (gc   > gr1) S[nt][2] = -1e30f;
                if (gc+1 > gr1) S[nt][3] = -1e30f;
            }
        }

        // ---- online softmax, fully in registers ----
        float mx0 = -1e30f, mx1 = -1e30f;
        #pragma unroll
        for (int nt = 0; nt < 8; nt++) {
            mx0 = fmaxf(mx0, fmaxf(S[nt][0], S[nt][1]));
            mx1 = fmaxf(mx1, fmaxf(S[nt][2], S[nt][3]));
        }
        mx0 = fmaxf(mx0, __shfl_xor_sync(0xffffffffu, mx0, 1));
        mx0 = fmaxf(mx0, __shfl_xor_sync(0xffffffffu, mx0, 2));
        mx1 = fmaxf(mx1, __shfl_xor_sync(0xffffffffu, mx1, 1));
        mx1 = fmaxf(mx1, __shfl_xor_sync(0xffffffffu, mx1, 2));
        const float mn0 = fmaxf(m0, mx0), mn1 = fmaxf(m1, mx1);
        const float al0 = __expf(m0 - mn0), al1 = __expf(m1 - mn1);
        float ps0 = 0.0f, ps1 = 0.0f;
        #pragma unroll
        for (int nt = 0; nt < 8; nt++) {
            S[nt][0] = f2tf(__expf(S[nt][0] - mn0)); ps0 += S[nt][0];
            S[nt][1] = f2tf(__expf(S[nt][1] - mn0)); ps0 += S[nt][1];
            S[nt][2] = f2tf(__expf(S[nt][2] - mn1)); ps1 += S[nt][2];
            S[nt][3] = f2tf(__expf(S[nt][3] - mn1)); ps1 += S[nt][3];
        }
        ps0 += __shfl_xor_sync(0xffffffffu, ps0, 1);
        ps0 += __shfl_xor_sync(0xffffffffu, ps0, 2);
        ps1 += __shfl_xor_sync(0xffffffffu, ps1, 1);
        ps1 += __shfl_xor_sync(0xffffffffu, ps1, 2);
        l0 = l0*al0 + ps0;  m0 = mn0;
        l1 = l1*al1 + ps1;  m1 = mn1;
        #pragma unroll
        for (int nt = 0; nt < 4; nt++) {
            O[nt][0] *= al0; O[nt][1] *= al0;
            O[nt][2] *= al1; O[nt][3] *= al1;
        }

        // ---- O += P V: permute P (C-frag) -> A-frag via quad shuffles ----
        #pragma unroll
        for (int kt = 0; kt < 8; kt++) {
            float x0, x1;
            unsigned a[4];
            x0 = __shfl_sync(0xffffffffu, S[kt][0], s0l);
            x1 = __shfl_sync(0xffffffffu, S[kt][1], s0l);
            a[0] = __float_as_uint(odd ? x1 : x0);
            x0 = __shfl_sync(0xffffffffu, S[kt][2], s0l);
            x1 = __shfl_sync(0xffffffffu, S[kt][3], s0l);
            a[1] = __float_as_uint(odd ? x1 : x0);
            x0 = __shfl_sync(0xffffffffu, S[kt][0], s1l);
            x1 = __shfl_sync(0xffffffffu, S[kt][1], s1l);
            a[2] = __float_as_uint(odd ? x1 : x0);
            x0 = __shfl_sync(0xffffffffu, S[kt][2], s1l);
            x1 = __shfl_sync(0xffffffffu, S[kt][3], s1l);
            a[3] = __float_as_uint(odd ? x1 : x0);

            const int kk = kt*8;
            #pragma unroll
            for (int nt = 0; nt < 4; nt++) {
                const int c = nt*8 + g;
                unsigned b[2];
                b[0] = __float_as_uint(Vs[(kk+tg  )*40 + c]);
                b[1] = __float_as_uint(Vs[(kk+tg+4)*40 + c]);
                mma_tf32(O[nt], a, b);
            }
        }
        __syncthreads();   // protect Ks/Vs before next tile's loads
    }

    // ---- normalize + store to g_A (n, c=h*32+d, t) ----
    const float inv0 = 1.0f / l0, inv1 = 1.0f / l1;
    const int n = nh >> 3, h = nh & 7;
    const int t_lo = qtile*128 + wid*16 + g;
    const int t_hi = t_lo + 8;
    #pragma unroll
    for (int nt = 0; nt < 4; nt++) {
        int ch = h*DVH + nt*8 + tg*2;
        g_A[((size_t)n*OC + ch  )*TL + t_lo] = O[nt][0] * inv0;
        g_A[((size_t)n*OC + ch+1)*TL + t_lo] = O[nt][1] * inv0;
        g_A[((size_t)n*OC + ch  )*TL + t_hi] = O[nt][2] * inv1;
        g_A[((size_t)n*OC + ch+1)*TL + t_hi] = O[nt][3] * inv1;
    }
}

// ---------------------------------------------------------------------------
// Output projection (tensor cores)
// ---------------------------------------------------------------------------
__global__ __launch_bounds__(256) void oproj_mma(
    const float* __restrict__ Wo, const float* __restrict__ bo,
    float* __restrict__ out)
{
    __shared__ float As[64][36];
    __shared__ float Bs[32][136];

    const int n  = blockIdx.z;
    const int m0 = blockIdx.y * 64;
    const int t0 = blockIdx.x * 128;
    const int tid = threadIdx.x;
    const int wid = tid >> 5, lane = tid & 31;
    const int g = lane >> 2, tg = lane & 3;
    const int wm = wid & 1, wn = wid >> 1;
    const float* Ab = g_A + (size_t)n * OC * TL;

    float C[2][4][4] = {};

    for (int k0 = 0; k0 < OC; k0 += 32) {
        #pragma unroll
        for (int l = 0; l < 2; l++) {
            int slot = tid + l*256;
            int m = slot >> 3, kg = slot & 7;
            float4 v = *(const float4*)(Wo + (size_t)(m0+m)*OC + k0 + kg*4);
            As[m][kg*4+0] = f2tf(v.x);
            As[m][kg*4+1] = f2tf(v.y);
            As[m][kg*4+2] = f2tf(v.z);
            As[m][kg*4+3] = f2tf(v.w);
        }
        #pragma unroll
        for (int l = 0; l < 4; l++) {
            int slot = tid + l*256;
            int k = slot >> 5, ng = slot & 31;
            float4 v = *(const float4*)(Ab + (size_t)(k0+k)*TL + t0 + ng*4);
            Bs[k][ng*4+0] = f2tf(v.x);
            Bs[k][ng*4+1] = f2tf(v.y);
            Bs[k][ng*4+2] = f2tf(v.z);
            Bs[k][ng*4+3] = f2tf(v.w);
        }
        __syncthreads();

        #pragma unroll
        for (int ks = 0; ks < 4; ks++) {
            const int kk = ks * 8;
            unsigned a[2][4];
            #pragma unroll
            for (int i = 0; i < 2; i++) {
                int r = wm*32 + i*16 + g;
                a[i][0] = __float_as_uint(As[r  ][kk+tg  ]);
                a[i][1] = __float_as_uint(As[r+8][kk+tg  ]);
                a[i][2] = __float_as_uint(As[r  ][kk+tg+4]);
                a[i][3] = __float_as_uint(As[r+8][kk+tg+4]);
            }
            unsigned b[4][2];
            #pragma unroll
            for (int j = 0; j < 4; j++) {
                int c = wn*32 + j*8 + g;
                b[j][0] = __float_as_uint(Bs[kk+tg  ][c]);
                b[j][1] = __float_as_uint(Bs[kk+tg+4][c]);
            }
            #pragma unroll
            for (int i = 0; i < 2; i++)
                #pragma unroll
                for (int j = 0; j < 4; j++)
                    mma_tf32(C[i][j], a[i], b[j]);
        }
        __syncthreads();
    }

    #pragma unroll
    for (int i = 0; i < 2; i++) {
        int r0 = m0 + wm*32 + i*16 + g;
        float b_lo = bo[r0], b_hi = bo[r0+8];
        #pragma unroll
        for (int j = 0; j < 4; j++) {
            int c = t0 + wn*32 + j*8 + tg*2;
            out[((size_t)n*OC + r0  )*TL + c  ] = C[i][j][0] + b_lo;
            out[((size_t)n*OC + r0  )*TL + c+1] = C[i][j][1] + b_lo;
            out[((size_t)n*OC + r0+8)*TL + c  ] = C[i][j][2] + b_hi;
            out[((size_t)n*OC + r0+8)*TL + c+1] = C[i][j][3] + b_hi;
        }
    }
}

// ---------------------------------------------------------------------------
extern "C" void kernel_launch(void* const* d_in, const int* in_sizes, int n_in,
                              void* d_out, int out_size)
{
    const float* x   = (const float*)d_in[0];
    const float* Wq  = (const float*)d_in[1];
    const float* bq  = (const float*)d_in[2];
    const float* Wkv = (const float*)d_in[3];
    const float* bkv = (const float*)d_in[4];
    const float* Wo  = (const float*)d_in[5];
    const float* bo  = (const float*)d_in[6];
    float* out = (float*)d_out;

    // 1) QKV: M=1280 (20 tiles of 64), N=1024 (8 tiles of 128), per batch
    qkv_mma<<<dim3(8, 20, NB), 256>>>(x, Wq, bq, Wkv, bkv);

    // 2) flash attention: Q tiles of 128 rows (8), 64 (n,h) pairs
    size_t smem = (size_t)(128*68) * sizeof(float);   // Qs overlays Ks+Vs
    attn_mma2<<<dim3(8, 64), 256, smem>>>();

    // 3) O proj: M=256 (4 tiles), N=1024 (8 tiles)
    oproj_mma<<<dim3(8, 4, NB), 256>>>(Wo, bo, out);
}

// round 5
// speedup vs baseline: 3.9661x; 1.0470x over previous
#include <cuda_runtime.h>

#define NB 8
#define CI 256
#define TL 1024
#define EMB 512
#define OC 256
#define NH 8
#define DH 64
#define DVH 32

// Scratch (device globals — no allocation allowed)
__device__ float g_Q[NB*NH*TL*DH];   // (n,h,t,64)
__device__ float g_K[NB*NH*TL*DH];   // (n,h,t,64)
__device__ float g_V[NB*NH*TL*DVH];  // (n,h,t,32)
__device__ float g_A[NB*OC*TL];      // attention output, (n,c,t)

// ---------------------------------------------------------------------------
// tf32 helpers
// ---------------------------------------------------------------------------
__device__ __forceinline__ float f2tf(float f) {
    unsigned u;
    asm("cvt.rna.tf32.f32 %0, %1;" : "=r"(u) : "f"(f));
    return __uint_as_float(u);
}

__device__ __forceinline__ void mma_tf32(float c[4], const unsigned a[4], const unsigned b[2]) {
    asm volatile(
        "mma.sync.aligned.m16n8k8.row.col.f32.tf32.tf32.f32 "
        "{%0,%1,%2,%3}, {%4,%5,%6,%7}, {%8,%9}, {%0,%1,%2,%3};"
        : "+f"(c[0]), "+f"(c[1]), "+f"(c[2]), "+f"(c[3])
        : "r"(a[0]), "r"(a[1]), "r"(a[2]), "r"(a[3]),
          "r"(b[0]), "r"(b[1]));
}

// smem chunk sizes (floats) for the 128x128 projection kernels
#define A_CH (128*36)
#define B_CH (32*136)

// ---------------------------------------------------------------------------
// QKV projection: CTA 128(M) x 128(N), warp tile 32x64, K-chunks of 32,
// double-buffered smem.
// ---------------------------------------------------------------------------
__global__ __launch_bounds__(256) void qkv_mma(
    const float* __restrict__ x,
    const float* __restrict__ Wq,  const float* __restrict__ bq,
    const float* __restrict__ Wkv, const float* __restrict__ bkv)
{
    extern __shared__ float sm[];
    float* Asm = sm;              // 2 x 128 x 36
    float* Bsm = sm + 2*A_CH;     // 2 x 32 x 136

    const int n  = blockIdx.z;
    const int m0 = blockIdx.y * 128;
    const int t0 = blockIdx.x * 128;
    const int tid = threadIdx.x;
    const int wid = tid >> 5, lane = tid & 31;
    const int g = lane >> 2, tg = lane & 3;
    const int wm = wid & 3, wn = wid >> 2;   // warp: rows wm*32, cols wn*64
    const float* xb = x + (size_t)n * CI * TL;

    float C[2][8][4] = {};

    // chunk loader
    auto load_chunk = [&](int k0, int buf) {
        float* A_ = Asm + buf*A_CH;
        float* B_ = Bsm + buf*B_CH;
        #pragma unroll
        for (int l = 0; l < 4; l++) {
            int slot = tid + l*256;          // 1024 float4 slots (128x32)
            int m = slot >> 3, kg = slot & 7;
            int o = m0 + m;
            const float* Wr = (o < EMB) ? (Wq + (size_t)o*CI) : (Wkv + (size_t)(o-EMB)*CI);
            float4 v = *(const float4*)(Wr + k0 + kg*4);
            float4 w;
            w.x = f2tf(v.x); w.y = f2tf(v.y); w.z = f2tf(v.z); w.w = f2tf(v.w);
            *(float4*)(A_ + m*36 + kg*4) = w;
        }
        #pragma unroll
        for (int l = 0; l < 4; l++) {
            int slot = tid + l*256;          // 1024 float4 slots (32x128)
            int k = slot >> 5, ng = slot & 31;
            float4 v = *(const float4*)(xb + (size_t)(k0+k)*TL + t0 + ng*4);
            float4 w;
            w.x = f2tf(v.x); w.y = f2tf(v.y); w.z = f2tf(v.z); w.w = f2tf(v.w);
            *(float4*)(B_ + k*136 + ng*4) = w;
        }
    };

    load_chunk(0, 0);
    __syncthreads();

    const int NCH = CI / 32;   // 8
    for (int c = 0; c < NCH; c++) {
        if (c + 1 < NCH) load_chunk((c+1)*32, (c+1) & 1);
        const float* A_ = Asm + (c & 1)*A_CH;
        const float* B_ = Bsm + (c & 1)*B_CH;
        #pragma unroll
        for (int ks = 0; ks < 4; ks++) {
            const int kk = ks * 8;
            unsigned a[2][4];
            #pragma unroll
            for (int i = 0; i < 2; i++) {
                int r = wm*32 + i*16 + g;
                a[i][0] = __float_as_uint(A_[(r  )*36 + kk+tg  ]);
                a[i][1] = __float_as_uint(A_[(r+8)*36 + kk+tg  ]);
                a[i][2] = __float_as_uint(A_[(r  )*36 + kk+tg+4]);
                a[i][3] = __float_as_uint(A_[(r+8)*36 + kk+tg+4]);
            }
            unsigned b[8][2];
            #pragma unroll
            for (int j = 0; j < 8; j++) {
                int cc = wn*64 + j*8 + g;
                b[j][0] = __float_as_uint(B_[(kk+tg  )*136 + cc]);
                b[j][1] = __float_as_uint(B_[(kk+tg+4)*136 + cc]);
            }
            #pragma unroll
            for (int i = 0; i < 2; i++)
                #pragma unroll
                for (int j = 0; j < 8; j++)
                    mma_tf32(C[i][j], a[i], b[j]);
        }
        __syncthreads();
    }

    // epilogue: bias + scatter into multihead layouts
    #pragma unroll
    for (int i = 0; i < 2; i++) {
        #pragma unroll
        for (int j = 0; j < 8; j++) {
            #pragma unroll
            for (int v = 0; v < 4; v++) {
                int o = m0 + wm*32 + i*16 + g + ((v >= 2) ? 8 : 0);
                int t = t0 + wn*64 + j*8 + tg*2 + (v & 1);
                float bias = (o < EMB) ? bq[o] : bkv[o - EMB];
                float val = C[i][j][v] + bias;
                if (o < EMB) {
                    int h = o >> 6, d = o & 63;
                    g_Q[(((size_t)n*NH + h)*TL + t)*DH + d] = val;
                } else if (o < 2*EMB) {
                    int oo = o - EMB;
                    int h = oo >> 6, d = oo & 63;
                    g_K[(((size_t)n*NH + h)*TL + t)*DH + d] = val;
                } else {
                    int oo = o - 2*EMB;
                    int h = oo >> 5, d = oo & 31;
                    g_V[(((size_t)n*NH + h)*TL + t)*DVH + d] = val;
                }
            }
        }
    }
}

// ---------------------------------------------------------------------------
// Causal flash attention: 4 warps x 32 Q-rows, S/P in registers.
// K/V b-fragments shared across 2 m-tiles per warp.
// ---------------------------------------------------------------------------
__global__ __launch_bounds__(128) void attn_mma3()
{
    extern __shared__ float sm[];
    float* Qs = sm;               // 128 x 68 (pre-loop only)
    float* Ks = sm;               // 64 x 68 (overlays Qs)
    float* Vs = sm + 64*68;       // 64 x 40

    const int qtile = 7 - blockIdx.x;   // heavy tiles first
    const int nh    = blockIdx.y;
    const int tid = threadIdx.x;
    const int wid = tid >> 5, lane = tid & 31;
    const int g = lane >> 2, tg = lane & 3;
    const bool odd = (tg & 1);
    const int sbase = lane & ~3;
    const int s0l = sbase + (tg >> 1);
    const int s1l = s0l + 2;

    const float* Qb = g_Q + ((size_t)nh*TL + qtile*128) * DH;
    const float* Kb = g_K + (size_t)nh*TL*DH;
    const float* Vb = g_V + (size_t)nh*TL*DVH;

    // ---- load Q tile 128x64 (tf32, pre-scaled by 1/8) ----
    #pragma unroll
    for (int l = 0; l < 16; l++) {
        int slot = tid + l*128;              // 2048 float4 slots
        int s = slot >> 4, dg = slot & 15;
        float4 v = *(const float4*)(Qb + (size_t)s*DH + dg*4);
        float4 w;
        w.x = f2tf(v.x * 0.125f); w.y = f2tf(v.y * 0.125f);
        w.z = f2tf(v.z * 0.125f); w.w = f2tf(v.w * 0.125f);
        *(float4*)&Qs[s*68 + dg*4] = w;
    }
    __syncthreads();

    // ---- extract Q fragments: warp owns rows wid*32 .. +31 (2 m-tiles) ----
    unsigned Aq[2][8][4];
    #pragma unroll
    for (int i = 0; i < 2; i++) {
        const int r = wid*32 + i*16 + g;
        #pragma unroll
        for (int kt = 0; kt < 8; kt++) {
            const int kk = kt*8;
            Aq[i][kt][0] = __float_as_uint(Qs[(r  )*68 + kk+tg  ]);
            Aq[i][kt][1] = __float_as_uint(Qs[(r+8)*68 + kk+tg  ]);
            Aq[i][kt][2] = __float_as_uint(Qs[(r  )*68 + kk+tg+4]);
            Aq[i][kt][3] = __float_as_uint(Qs[(r+8)*68 + kk+tg+4]);
        }
    }
    __syncthreads();   // Qs region reused for K

    float mr[2][2] = {{-1e30f,-1e30f},{-1e30f,-1e30f}};
    float lr[2][2] = {{0,0},{0,0}};
    float O[2][4][4] = {};

    const int jmax = 2*qtile + 1;
    for (int j = 0; j <= jmax; j++) {
        // ---- load K (64x64) and V (64x32) ----
        const float* Kt = Kb + (size_t)j*64*DH;
        #pragma unroll
        for (int l = 0; l < 8; l++) {
            int slot = tid + l*128;
            int s = slot >> 4, dg = slot & 15;
            float4 v = *(const float4*)(Kt + (size_t)s*DH + dg*4);
            float4 w;
            w.x = f2tf(v.x); w.y = f2tf(v.y); w.z = f2tf(v.z); w.w = f2tf(v.w);
            *(float4*)&Ks[s*68 + dg*4] = w;
        }
        const float* Vt = Vb + (size_t)j*64*DVH;
        #pragma unroll
        for (int l = 0; l < 4; l++) {
            int slot = tid + l*128;
            int s = slot >> 3, dg = slot & 7;
            float4 v = *(const float4*)(Vt + (size_t)s*DVH + dg*4);
            float4 w;
            w.x = f2tf(v.x); w.y = f2tf(v.y); w.z = f2tf(v.z); w.w = f2tf(v.w);
            *(float4*)&Vs[s*40 + dg*4] = w;
        }
        __syncthreads();

        // ---- S = Q K^T: warp strip 32 x 64, b-frags shared across m-tiles ----
        float S[2][8][4] = {};
        #pragma unroll
        for (int ks = 0; ks < 8; ks++) {
            const int kk = ks*8;
            unsigned b[8][2];
            #pragma unroll
            for (int nt = 0; nt < 8; nt++) {
                const int c = nt*8 + g;
                b[nt][0] = __float_as_uint(Ks[c*68 + kk+tg  ]);
                b[nt][1] = __float_as_uint(Ks[c*68 + kk+tg+4]);
            }
            #pragma unroll
            for (int i = 0; i < 2; i++)
                #pragma unroll
                for (int nt = 0; nt < 8; nt++)
                    mma_tf32(S[i][nt], Aq[i][ks], b[nt]);
        }

        // ---- causal mask (near diagonal only) ----
        if (j >= 2*qtile) {
            #pragma unroll
            for (int i = 0; i < 2; i++) {
                const int gr0 = qtile*128 + wid*32 + i*16 + g;
                const int gr1 = gr0 + 8;
                #pragma unroll
                for (int nt = 0; nt < 8; nt++) {
                    const int gc = j*64 + nt*8 + tg*2;
                    if (gc   > gr0) S[i][nt][0] = -1e30f;
                    if (gc+1 > gr0) S[i][nt][1] = -1e30f;
                    if (gc   > gr1) S[i][nt][2] = -1e30f;
                    if (gc+1 > gr1) S[i][nt][3] = -1e30f;
                }
            }
        }

        // ---- online softmax per m-tile ----
        #pragma unroll
        for (int i = 0; i < 2; i++) {
            float mx0 = -1e30f, mx1 = -1e30f;
            #pragma unroll
            for (int nt = 0; nt < 8; nt++) {
                mx0 = fmaxf(mx0, fmaxf(S[i][nt][0], S[i][nt][1]));
                mx1 = fmaxf(mx1, fmaxf(S[i][nt][2], S[i][nt][3]));
            }
            mx0 = fmaxf(mx0, __shfl_xor_sync(0xffffffffu, mx0, 1));
            mx0 = fmaxf(mx0, __shfl_xor_sync(0xffffffffu, mx0, 2));
            mx1 = fmaxf(mx1, __shfl_xor_sync(0xffffffffu, mx1, 1));
            mx1 = fmaxf(mx1, __shfl_xor_sync(0xffffffffu, mx1, 2));
            const float mn0 = fmaxf(mr[i][0], mx0), mn1 = fmaxf(mr[i][1], mx1);
            const float al0 = __expf(mr[i][0] - mn0), al1 = __expf(mr[i][1] - mn1);
            float ps0 = 0.0f, ps1 = 0.0f;
            #pragma unroll
            for (int nt = 0; nt < 8; nt++) {
                S[i][nt][0] = f2tf(__expf(S[i][nt][0] - mn0)); ps0 += S[i][nt][0];
                S[i][nt][1] = f2tf(__expf(S[i][nt][1] - mn0)); ps0 += S[i][nt][1];
                S[i][nt][2] = f2tf(__expf(S[i][nt][2] - mn1)); ps1 += S[i][nt][2];
                S[i][nt][3] = f2tf(__expf(S[i][nt][3] - mn1)); ps1 += S[i][nt][3];
            }
            ps0 += __shfl_xor_sync(0xffffffffu, ps0, 1);
            ps0 += __shfl_xor_sync(0xffffffffu, ps0, 2);
            ps1 += __shfl_xor_sync(0xffffffffu, ps1, 1);
            ps1 += __shfl_xor_sync(0xffffffffu, ps1, 2);
            lr[i][0] = lr[i][0]*al0 + ps0;  mr[i][0] = mn0;
            lr[i][1] = lr[i][1]*al1 + ps1;  mr[i][1] = mn1;
            #pragma unroll
            for (int nt = 0; nt < 4; nt++) {
                O[i][nt][0] *= al0; O[i][nt][1] *= al0;
                O[i][nt][2] *= al1; O[i][nt][3] *= al1;
            }
        }

        // ---- O += P V: shuffle-permute P, b-frags shared across m-tiles ----
        #pragma unroll
        for (int kt = 0; kt < 8; kt++) {
            const int kk = kt*8;
            unsigned bv[4][2];
            #pragma unroll
            for (int nt = 0; nt < 4; nt++) {
                const int c = nt*8 + g;
                bv[nt][0] = __float_as_uint(Vs[(kk+tg  )*40 + c]);
                bv[nt][1] = __float_as_uint(Vs[(kk+tg+4)*40 + c]);
            }
            #pragma unroll
            for (int i = 0; i < 2; i++) {
                float x0, x1;
                unsigned a[4];
                x0 = __shfl_sync(0xffffffffu, S[i][kt][0], s0l);
                x1 = __shfl_sync(0xffffffffu, S[i][kt][1], s0l);
                a[0] = __float_as_uint(odd ? x1 : x0);
                x0 = __shfl_sync(0xffffffffu, S[i][kt][2], s0l);
                x1 = __shfl_sync(0xffffffffu, S[i][kt][3], s0l);
                a[1] = __float_as_uint(odd ? x1 : x0);
                x0 = __shfl_sync(0xffffffffu, S[i][kt][0], s1l);
                x1 = __shfl_sync(0xffffffffu, S[i][kt][1], s1l);
                a[2] = __float_as_uint(odd ? x1 : x0);
                x0 = __shfl_sync(0xffffffffu, S[i][kt][2], s1l);
                x1 = __shfl_sync(0xffffffffu, S[i][kt][3], s1l);
                a[3] = __float_as_uint(odd ? x1 : x0);
                #pragma unroll
                for (int nt = 0; nt < 4; nt++)
                    mma_tf32(O[i][nt], a, bv[nt]);
            }
        }
        __syncthreads();   // protect Ks/Vs before next tile
    }

    // ---- normalize + store to g_A (n, c=h*32+d, t) ----
    const int n = nh >> 3, h = nh & 7;
    #pragma unroll
    for (int i = 0; i < 2; i++) {
        const float inv0 = 1.0f / lr[i][0], inv1 = 1.0f / lr[i][1];
        const int t_lo = qtile*128 + wid*32 + i*16 + g;
        const int t_hi = t_lo + 8;
        #pragma unroll
        for (int nt = 0; nt < 4; nt++) {
            int ch = h*DVH + nt*8 + tg*2;
            g_A[((size_t)n*OC + ch  )*TL + t_lo] = O[i][nt][0] * inv0;
            g_A[((size_t)n*OC + ch+1)*TL + t_lo] = O[i][nt][1] * inv0;
            g_A[((size_t)n*OC + ch  )*TL + t_hi] = O[i][nt][2] * inv1;
            g_A[((size_t)n*OC + ch+1)*TL + t_hi] = O[i][nt][3] * inv1;
        }
    }
}

// ---------------------------------------------------------------------------
// Output projection: CTA 128x128, warp 32x64, double-buffered.
// ---------------------------------------------------------------------------
__global__ __launch_bounds__(256) void oproj_mma(
    const float* __restrict__ Wo, const float* __restrict__ bo,
    float* __restrict__ out)
{
    extern __shared__ float sm[];
    float* Asm = sm;
    float* Bsm = sm + 2*A_CH;

    const int n  = blockIdx.z;
    const int m0 = blockIdx.y * 128;
    const int t0 = blockIdx.x * 128;
    const int tid = threadIdx.x;
    const int wid = tid >> 5, lane = tid & 31;
    const int g = lane >> 2, tg = lane & 3;
    const int wm = wid & 3, wn = wid >> 2;
    const float* Ab = g_A + (size_t)n * OC * TL;

    float C[2][8][4] = {};

    auto load_chunk = [&](int k0, int buf) {
        float* A_ = Asm + buf*A_CH;
        float* B_ = Bsm + buf*B_CH;
        #pragma unroll
        for (int l = 0; l < 4; l++) {
            int slot = tid + l*256;
            int m = slot >> 3, kg = slot & 7;
            float4 v = *(const float4*)(Wo + (size_t)(m0+m)*OC + k0 + kg*4);
            float4 w;
            w.x = f2tf(v.x); w.y = f2tf(v.y); w.z = f2tf(v.z); w.w = f2tf(v.w);
            *(float4*)(A_ + m*36 + kg*4) = w;
        }
        #pragma unroll
        for (int l = 0; l < 4; l++) {
            int slot = tid + l*256;
            int k = slot >> 5, ng = slot & 31;
            float4 v = *(const float4*)(Ab + (size_t)(k0+k)*TL + t0 + ng*4);
            float4 w;
            w.x = f2tf(v.x); w.y = f2tf(v.y); w.z = f2tf(v.z); w.w = f2tf(v.w);
            *(float4*)(B_ + k*136 + ng*4) = w;
        }
    };

    load_chunk(0, 0);
    __syncthreads();

    const int NCH = OC / 32;   // 8
    for (int c = 0; c < NCH; c++) {
        if (c + 1 < NCH) load_chunk((c+1)*32, (c+1) & 1);
        const float* A_ = Asm + (c & 1)*A_CH;
        const float* B_ = Bsm + (c & 1)*B_CH;
        #pragma unroll
        for (int ks = 0; ks < 4; ks++) {
            const int kk = ks * 8;
            unsigned a[2][4];
            #pragma unroll
            for (int i = 0; i < 2; i++) {
                int r = wm*32 + i*16 + g;
                a[i][0] = __float_as_uint(A_[(r  )*36 + kk+tg  ]);
                a[i][1] = __float_as_uint(A_[(r+8)*36 + kk+tg  ]);
                a[i][2] = __float_as_uint(A_[(r  )*36 + kk+tg+4]);
                a[i][3] = __float_as_uint(A_[(r+8)*36 + kk+tg+4]);
            }
            unsigned b[8][2];
            #pragma unroll
            for (int j = 0; j < 8; j++) {
                int cc = wn*64 + j*8 + g;
                b[j][0] = __float_as_uint(B_[(kk+tg  )*136 + cc]);
                b[j][1] = __float_as_uint(B_[(kk+tg+4)*136 + cc]);
            }
            #pragma unroll
            for (int i = 0; i < 2; i++)
                #pragma unroll
                for (int j = 0; j < 8; j++)
                    mma_tf32(C[i][j], a[i], b[j]);
        }
        __syncthreads();
    }

    #pragma unroll
    for (int i = 0; i < 2; i++) {
        int r0 = m0 + wm*32 + i*16 + g;
        float b_lo = bo[r0], b_hi = bo[r0+8];
        #pragma unroll
        for (int j = 0; j < 8; j++) {
            int c = t0 + wn*64 + j*8 + tg*2;
            out[((size_t)n*OC + r0  )*TL + c  ] = C[i][j][0] + b_lo;
            out[((size_t)n*OC + r0  )*TL + c+1] = C[i][j][1] + b_lo;
            out[((size_t)n*OC + r0+8)*TL + c  ] = C[i][j][2] + b_hi;
            out[((size_t)n*OC + r0+8)*TL + c+1] = C[i][j][3] + b_hi;
        }
    }
}

// ---------------------------------------------------------------------------
extern "C" void kernel_launch(void* const* d_in, const int* in_sizes, int n_in,
                              void* d_out, int out_size)
{
    const float* x   = (const float*)d_in[0];
    const float* Wq  = (const float*)d_in[1];
    const float* bq  = (const float*)d_in[2];
    const float* Wkv = (const float*)d_in[3];
    const float* bkv = (const float*)d_in[4];
    const float* Wo  = (const float*)d_in[5];
    const float* bo  = (const float*)d_in[6];
    float* out = (float*)d_out;

    const size_t gemm_smem = (size_t)(2*A_CH + 2*B_CH) * sizeof(float);  // ~70KB
    cudaFuncSetAttribute(qkv_mma,
                         cudaFuncAttributeMaxDynamicSharedMemorySize, (int)gemm_smem);
    cudaFuncSetAttribute(oproj_mma,
                         cudaFuncAttributeMaxDynamicSharedMemorySize, (int)gemm_smem);

    // 1) QKV: M=1280 (10 tiles of 128), N=1024 (8 tiles of 128), per batch
    qkv_mma<<<dim3(8, 10, NB), 256, gemm_smem>>>(x, Wq, bq, Wkv, bkv);

    // 2) flash attention: 8 Q-tiles of 128 rows, 64 (n,h) pairs, 128 threads
    size_t attn_smem = (size_t)(128*68) * sizeof(float);
    attn_mma3<<<dim3(8, 64), 128, attn_smem>>>();

    // 3) O proj: M=256 (2 tiles), N=1024 (8 tiles)
    oproj_mma<<<dim3(8, 2, NB), 256, gemm_smem>>>(Wo, bo, out);
}